// round 12
// baseline (speedup 1.0000x reference)
#include <cuda_runtime.h>

#define NN 100000
#define EE 1000000
#define DHH 64
#define KCH 8
#define LNUM 3

struct Edge { int c; float v; };

// ---------------- device scratch (static, no allocation) ----------------
__device__ float g_T[KCH][NN * DHH];     // Chebyshev basis buffers T0..T7 (~205 MB)
__device__ float g_deg[NN];
__device__ float g_dinv[NN];
__device__ int   g_cnt[NN];
__device__ int   g_rowptr[NN + 1];
__device__ int   g_wp[NN];
__device__ Edge  g_edge[EE];             // CSR(dst): packed (src, norm) per edge
__device__ int   g_sums[128];
__device__ int   g_offs[128];

// ---------------- f32x2 packed-math helpers (Blackwell, PTX-only) ----------------
__device__ __forceinline__ unsigned long long ffma2(unsigned long long a,
                                                    unsigned long long b,
                                                    unsigned long long c) {
    unsigned long long d;
    asm("fma.rn.f32x2 %0, %1, %2, %3;" : "=l"(d) : "l"(a), "l"(b), "l"(c));
    return d;
}
__device__ __forceinline__ unsigned long long splat2(float f) {
    unsigned long long d; unsigned int u = __float_as_uint(f);
    asm("mov.b64 %0, {%1, %1};" : "=l"(d) : "r"(u));
    return d;
}
__device__ __forceinline__ float lo2(unsigned long long v) {
    return __uint_as_float((unsigned int)(v & 0xffffffffull));
}
__device__ __forceinline__ float hi2(unsigned long long v) {
    return __uint_as_float((unsigned int)(v >> 32));
}

// evict-first 128b store for write-once data
__device__ __forceinline__ void stg_cs(float4* p, float4 v) {
    asm volatile("st.global.cs.v4.f32 [%0], {%1, %2, %3, %4};"
                 :: "l"(p), "f"(v.x), "f"(v.y), "f"(v.z), "f"(v.w) : "memory");
}

// ---------------- setup kernels ----------------
__global__ void k_zero() {
    int i = blockIdx.x * blockDim.x + threadIdx.x;
    if (i < NN) { g_deg[i] = 0.f; g_cnt[i] = 0; }
}

// degree over src (weights, self-loops removed) + in-degree count over dst
__global__ void k_degcnt(const int* __restrict__ ei, const float* __restrict__ ew) {
    int e = blockIdx.x * blockDim.x + threadIdx.x;
    if (e >= EE) return;
    int s = ei[e], d = ei[EE + e];
    float w = (s == d) ? 0.f : ew[e];
    if (w != 0.f) atomicAdd(&g_deg[s], w);
    atomicAdd(&g_cnt[d], 1);
}

__global__ void k_dinv() {
    int i = blockIdx.x * blockDim.x + threadIdx.x;
    if (i < NN) {
        float d = g_deg[i];
        g_dinv[i] = (d > 0.f) ? rsqrtf(d) : 0.f;
    }
}

// ---------------- 2-level exclusive scan over g_cnt -> g_rowptr ----------------
__global__ void k_blocksum() {
    __shared__ int s[1024];
    int idx = blockIdx.x * 1024 + threadIdx.x;
    s[threadIdx.x] = (idx < NN) ? g_cnt[idx] : 0;
    __syncthreads();
    for (int off = 512; off > 0; off >>= 1) {
        if (threadIdx.x < off) s[threadIdx.x] += s[threadIdx.x + off];
        __syncthreads();
    }
    if (threadIdx.x == 0) g_sums[blockIdx.x] = s[0];
}

__global__ void k_scansums(int nb) {
    if (threadIdx.x == 0) {
        int acc = 0;
        for (int b = 0; b < nb; b++) { g_offs[b] = acc; acc += g_sums[b]; }
    }
}

__global__ void k_scanblock() {
    __shared__ int s[1024];
    int tid = threadIdx.x;
    int idx = blockIdx.x * 1024 + tid;
    int v = (idx < NN) ? g_cnt[idx] : 0;
    s[tid] = v;
    __syncthreads();
    for (int off = 1; off < 1024; off <<= 1) {
        int t = (tid >= off) ? s[tid - off] : 0;
        __syncthreads();
        s[tid] += t;
        __syncthreads();
    }
    if (idx < NN) {
        int ex = s[tid] - v + g_offs[blockIdx.x];   // exclusive
        g_rowptr[idx] = ex;
        g_wp[idx]     = ex;
    }
    if (blockIdx.x == 0 && tid == 0) g_rowptr[NN] = EE;
}

// scatter edges into CSR(dst) with precomputed norm values
__global__ void k_fill(const int* __restrict__ ei, const float* __restrict__ ew) {
    int e = blockIdx.x * blockDim.x + threadIdx.x;
    if (e >= EE) return;
    int s = ei[e], d = ei[EE + e];
    float w = (s == d) ? 0.f : ew[e];
    float v = -g_dinv[s] * w * g_dinv[d];
    int p = atomicAdd(&g_wp[d], 1);
    Edge ed; ed.c = s; ed.v = v;
    g_edge[p] = ed;
}

__global__ void k_copy(const float4* __restrict__ x) {
    int i = blockIdx.x * blockDim.x + threadIdx.x;
    if (i < NN * DHH / 4) ((float4*)g_T[0])[i] = x[i];
}

// ---------------- propagation: Tout = scale * (L_hat @ Tin) - Tsub ----------------
// half-warp (16 lanes) per node; lane l owns float4 of features [4l, 4l+4).
// Edge metadata read as uniform (broadcast) 8B loads — no shuffles.
// Tsub streaming load issued BEFORE the gather loop so its latency overlaps.
template <bool HAS_SUB>
__global__ void __launch_bounds__(256) k_prop(const float* __restrict__ Tin,
                                              float* __restrict__ Tout,
                                              const float* __restrict__ Tsub) {
    int gt     = blockIdx.x * blockDim.x + threadIdx.x;
    int node   = gt >> 4;
    int lane16 = threadIdx.x & 15;
    if (node >= NN) return;

    float4 s = make_float4(0.f, 0.f, 0.f, 0.f);
    if (HAS_SUB) s = ((const float4*)(Tsub + node * DHH))[lane16];   // early issue

    float4 acc = make_float4(0.f, 0.f, 0.f, 0.f);
    int beg = g_rowptr[node], end = g_rowptr[node + 1];
#pragma unroll 8
    for (int e = beg; e < end; e++) {
        Edge ed = g_edge[e];                       // uniform across the 16-lane group
        float4 h = ((const float4*)(Tin + ed.c * DHH))[lane16];
        acc.x += ed.v * h.x;  acc.y += ed.v * h.y;
        acc.z += ed.v * h.z;  acc.w += ed.v * h.w;
    }
    float4* op = (float4*)(Tout + node * DHH);
    if (HAS_SUB) {
        op[lane16] = make_float4(2.f * acc.x - s.x, 2.f * acc.y - s.y,
                                 2.f * acc.z - s.z, 2.f * acc.w - s.w);
    } else {
        op[lane16] = acc;
    }
}

// ---------------- fused GEMM: out = relu( sum_k T_k @ W_k + b ) ----------------
// block: 64 rows x 64 cols, 256 threads, 4x4 microtile, packed f32x2 FMA,
// register-buffered software pipeline over the 8 Chebyshev basis blocks.
#define SPITCH 68   // floats per smem row (16B-aligned, padded)
template <bool LAST>
__global__ void __launch_bounds__(256) k_gemm(const float* __restrict__ Wl,
                                              const float* __restrict__ bl,
                                              float* __restrict__ out) {
    __shared__ float Ts[64 * SPITCH];
    __shared__ float Ws[64 * SPITCH];
    int tid = threadIdx.x;
    int r0  = blockIdx.x * 64;
    int ty  = tid >> 4;     // 0..15 -> row group
    int tx  = tid & 15;     // 0..15 -> col group
    // acc2[rr][p]: packed pair of fp32 accumulators for cols (tx*4+2p, tx*4+2p+1)
    unsigned long long acc2[4][2] = {};
    bool full = (r0 + 64 <= NN);

    // each thread stages 4 float4 per tile: items i = tid + j*256, j=0..3
    int srow[4], sq[4];
#pragma unroll
    for (int j = 0; j < 4; j++) {
        int i = tid + j * 256;
        srow[j] = i >> 4;
        sq[j]   = i & 15;
    }

    float4 tReg[4], wReg[4];
    // preload k = 0
    {
        const float* Tk = g_T[0];
        const float* Wk = Wl;
#pragma unroll
        for (int j = 0; j < 4; j++) {
            int gr = r0 + srow[j];
            tReg[j] = (full || gr < NN) ? ((const float4*)(Tk + gr * 64))[sq[j]]
                                        : make_float4(0.f, 0.f, 0.f, 0.f);
            wReg[j] = ((const float4*)(Wk + srow[j] * 64))[sq[j]];
        }
    }

    for (int k = 0; k < KCH; k++) {
        // commit staged registers to smem
        __syncthreads();
#pragma unroll
        for (int j = 0; j < 4; j++) {
            ((float4*)(Ts + srow[j] * SPITCH))[sq[j]] = tReg[j];
            ((float4*)(Ws + srow[j] * SPITCH))[sq[j]] = wReg[j];
        }
        __syncthreads();

        // prefetch k+1 while computing k
        if (k + 1 < KCH) {
            const float* Tk = g_T[k + 1];
            const float* Wk = Wl + (k + 1) * 64 * 64;
#pragma unroll
            for (int j = 0; j < 4; j++) {
                int gr = r0 + srow[j];
                tReg[j] = (full || gr < NN) ? ((const float4*)(Tk + gr * 64))[sq[j]]
                                            : make_float4(0.f, 0.f, 0.f, 0.f);
                wReg[j] = ((const float4*)(Wk + srow[j] * 64))[sq[j]];
            }
        }

#pragma unroll 8
        for (int f = 0; f < 64; f++) {
            // 4 W values for this thread's cols, as 2 packed b64 (LDS.128)
            ulonglong2 wv2 = *(const ulonglong2*)(Ws + f * SPITCH + tx * 4);
            unsigned long long tv2[4];
#pragma unroll
            for (int rr = 0; rr < 4; rr++)
                tv2[rr] = splat2(Ts[(ty * 4 + rr) * SPITCH + f]);
#pragma unroll
            for (int rr = 0; rr < 4; rr++) {
                acc2[rr][0] = ffma2(tv2[rr], wv2.x, acc2[rr][0]);
                acc2[rr][1] = ffma2(tv2[rr], wv2.y, acc2[rr][1]);
            }
        }
    }

    float4 bv = ((const float4*)bl)[tx];
#pragma unroll
    for (int rr = 0; rr < 4; rr++) {
        int gr = r0 + ty * 4 + rr;
        if (gr < NN) {
            float4 o;
            o.x = fmaxf(lo2(acc2[rr][0]) + bv.x, 0.f);
            o.y = fmaxf(hi2(acc2[rr][0]) + bv.y, 0.f);
            o.z = fmaxf(lo2(acc2[rr][1]) + bv.z, 0.f);
            o.w = fmaxf(hi2(acc2[rr][1]) + bv.w, 0.f);
            float4* p = (float4*)(out + gr * 64) + tx;
            if (LAST) stg_cs(p, o);    // final output: never re-read, evict first
            else      *p = o;          // becomes next layer's T0: keep in L2
        }
    }
}

// ---------------- launch ----------------
extern "C" void kernel_launch(void* const* d_in, const int* in_sizes, int n_in,
                              void* d_out, int out_size) {
    const float* x  = (const float*)d_in[0];
    const int*   ei = (const int*)d_in[1];
    const float* ew = (const float*)d_in[2];
    const float* W  = (const float*)d_in[3];
    const float* b  = (const float*)d_in[4];
    float* out = (float*)d_out;

    float* Tbase = nullptr;
    cudaGetSymbolAddress((void**)&Tbase, g_T);
    auto Tk = [&](int k) { return Tbase + (size_t)k * NN * DHH; };

    const int TB = 256;
    int gN = (NN + TB - 1) / TB;
    int gE = (EE + TB - 1) / TB;
    int nb = (NN + 1023) / 1024;

    // CSR(dst) + edge norms
    k_zero<<<gN, TB>>>();
    k_degcnt<<<gE, TB>>>(ei, ew);
    k_dinv<<<gN, TB>>>();
    k_blocksum<<<nb, 1024>>>();
    k_scansums<<<1, 32>>>(nb);
    k_scanblock<<<nb, 1024>>>();
    k_fill<<<gE, TB>>>(ei, ew);

    // h -> T0
    k_copy<<<(NN * DHH / 4 + TB - 1) / TB, TB>>>((const float4*)x);

    int gProp = (NN * 16 + TB - 1) / TB;   // half-warp per node
    int gGemm = (NN + 63) / 64;

    for (int l = 0; l < LNUM; l++) {
        const float* Wl = W + (size_t)l * KCH * 64 * 64;
        const float* bl = b + l * 64;

        // T1 = L_hat @ T0
        k_prop<false><<<gProp, TB>>>(Tk(0), Tk(1), nullptr);
        // Tk = 2 * L_hat @ T(k-1) - T(k-2)
        for (int k = 2; k < KCH; k++)
            k_prop<true><<<gProp, TB>>>(Tk(k - 1), Tk(k), Tk(k - 2));

        if (l == LNUM - 1) k_gemm<true><<<gGemm, TB>>>(Wl, bl, out);
        else               k_gemm<false><<<gGemm, TB>>>(Wl, bl, Tk(0));
    }
}

// round 16
// speedup vs baseline: 1.0908x; 1.0908x over previous
#include <cuda_runtime.h>
#include <cuda_fp16.h>

#define NN 100000
#define EE 1000000
#define DHH 64
#define KCH 8
#define LNUM 3

struct Edge { int c; float v; };

// ---------------- device scratch (static, no allocation) ----------------
__device__ __half g_T[KCH][NN * DHH];    // Chebyshev basis T0..T7 in fp16 (~102 MB)
__device__ float  g_deg[NN];
__device__ float  g_dinv[NN];
__device__ int    g_cnt[NN];
__device__ int    g_rowptr[NN + 1];
__device__ int    g_wp[NN];
__device__ Edge   g_edge[EE];            // CSR(dst): packed (src, norm) per edge
__device__ int    g_sums[128];
__device__ int    g_offs[128];

// ---------------- half4 <-> float4 helpers ----------------
__device__ __forceinline__ float4 h2f4(uint2 u) {
    __half2 a = *reinterpret_cast<__half2*>(&u.x);
    __half2 b = *reinterpret_cast<__half2*>(&u.y);
    float2 fa = __half22float2(a), fb = __half22float2(b);
    return make_float4(fa.x, fa.y, fb.x, fb.y);
}
__device__ __forceinline__ uint2 f2h4(float4 v) {
    __half2 a = __floats2half2_rn(v.x, v.y);
    __half2 b = __floats2half2_rn(v.z, v.w);
    uint2 u;
    u.x = *reinterpret_cast<unsigned int*>(&a);
    u.y = *reinterpret_cast<unsigned int*>(&b);
    return u;
}

// ---------------- f32x2 packed-math helpers (Blackwell, PTX-only) ----------------
__device__ __forceinline__ unsigned long long ffma2(unsigned long long a,
                                                    unsigned long long b,
                                                    unsigned long long c) {
    unsigned long long d;
    asm("fma.rn.f32x2 %0, %1, %2, %3;" : "=l"(d) : "l"(a), "l"(b), "l"(c));
    return d;
}
__device__ __forceinline__ unsigned long long splat2(float f) {
    unsigned long long d; unsigned int u = __float_as_uint(f);
    asm("mov.b64 %0, {%1, %1};" : "=l"(d) : "r"(u));
    return d;
}
__device__ __forceinline__ float lo2(unsigned long long v) {
    return __uint_as_float((unsigned int)(v & 0xffffffffull));
}
__device__ __forceinline__ float hi2(unsigned long long v) {
    return __uint_as_float((unsigned int)(v >> 32));
}

// evict-first 128b store for write-once data
__device__ __forceinline__ void stg_cs(float4* p, float4 v) {
    asm volatile("st.global.cs.v4.f32 [%0], {%1, %2, %3, %4};"
                 :: "l"(p), "f"(v.x), "f"(v.y), "f"(v.z), "f"(v.w) : "memory");
}

// ---------------- setup kernels ----------------
__global__ void k_zero() {
    int i = blockIdx.x * blockDim.x + threadIdx.x;
    if (i < NN) { g_deg[i] = 0.f; g_cnt[i] = 0; }
}

__global__ void k_degcnt(const int* __restrict__ ei, const float* __restrict__ ew) {
    int e = blockIdx.x * blockDim.x + threadIdx.x;
    if (e >= EE) return;
    int s = ei[e], d = ei[EE + e];
    float w = (s == d) ? 0.f : ew[e];
    if (w != 0.f) atomicAdd(&g_deg[s], w);
    atomicAdd(&g_cnt[d], 1);
}

__global__ void k_dinv() {
    int i = blockIdx.x * blockDim.x + threadIdx.x;
    if (i < NN) {
        float d = g_deg[i];
        g_dinv[i] = (d > 0.f) ? rsqrtf(d) : 0.f;
    }
}

// ---------------- 2-level exclusive scan over g_cnt -> g_rowptr ----------------
__global__ void k_blocksum() {
    __shared__ int s[1024];
    int idx = blockIdx.x * 1024 + threadIdx.x;
    s[threadIdx.x] = (idx < NN) ? g_cnt[idx] : 0;
    __syncthreads();
    for (int off = 512; off > 0; off >>= 1) {
        if (threadIdx.x < off) s[threadIdx.x] += s[threadIdx.x + off];
        __syncthreads();
    }
    if (threadIdx.x == 0) g_sums[blockIdx.x] = s[0];
}

__global__ void k_scansums(int nb) {
    if (threadIdx.x == 0) {
        int acc = 0;
        for (int b = 0; b < nb; b++) { g_offs[b] = acc; acc += g_sums[b]; }
    }
}

__global__ void k_scanblock() {
    __shared__ int s[1024];
    int tid = threadIdx.x;
    int idx = blockIdx.x * 1024 + tid;
    int v = (idx < NN) ? g_cnt[idx] : 0;
    s[tid] = v;
    __syncthreads();
    for (int off = 1; off < 1024; off <<= 1) {
        int t = (tid >= off) ? s[tid - off] : 0;
        __syncthreads();
        s[tid] += t;
        __syncthreads();
    }
    if (idx < NN) {
        int ex = s[tid] - v + g_offs[blockIdx.x];   // exclusive
        g_rowptr[idx] = ex;
        g_wp[idx]     = ex;
    }
    if (blockIdx.x == 0 && tid == 0) g_rowptr[NN] = EE;
}

__global__ void k_fill(const int* __restrict__ ei, const float* __restrict__ ew) {
    int e = blockIdx.x * blockDim.x + threadIdx.x;
    if (e >= EE) return;
    int s = ei[e], d = ei[EE + e];
    float w = (s == d) ? 0.f : ew[e];
    float v = -g_dinv[s] * w * g_dinv[d];
    int p = atomicAdd(&g_wp[d], 1);
    Edge ed; ed.c = s; ed.v = v;
    g_edge[p] = ed;
}

// x (fp32) -> T0 (fp16)
__global__ void k_copy(const float4* __restrict__ x) {
    int i = blockIdx.x * blockDim.x + threadIdx.x;
    if (i < NN * DHH / 4) {
        ((uint2*)g_T[0])[i] = f2h4(x[i]);
    }
}

// ---------------- propagation: Tout = 2*(L_hat @ Tin) - Tsub (or 1x, no sub) ----
// half-warp (16 lanes) per node; lane l owns 4 halfs (8B) of the 128B row.
// Edge metadata read as uniform (broadcast) 8B loads — no shuffles.
// Accumulation in fp32; T stored fp16.
template <bool HAS_SUB>
__global__ void __launch_bounds__(256) k_prop(const __half* __restrict__ Tin,
                                              __half* __restrict__ Tout,
                                              const __half* __restrict__ Tsub) {
    int gt     = blockIdx.x * blockDim.x + threadIdx.x;
    int node   = gt >> 4;
    int lane16 = threadIdx.x & 15;
    if (node >= NN) return;

    float4 s = make_float4(0.f, 0.f, 0.f, 0.f);
    if (HAS_SUB) s = h2f4(((const uint2*)(Tsub + node * DHH))[lane16]);  // early issue

    float4 acc = make_float4(0.f, 0.f, 0.f, 0.f);
    int beg = g_rowptr[node], end = g_rowptr[node + 1];
#pragma unroll 8
    for (int e = beg; e < end; e++) {
        Edge ed = g_edge[e];                       // uniform across the 16-lane group
        float4 h = h2f4(((const uint2*)(Tin + ed.c * DHH))[lane16]);
        acc.x += ed.v * h.x;  acc.y += ed.v * h.y;
        acc.z += ed.v * h.z;  acc.w += ed.v * h.w;
    }
    uint2* op = (uint2*)(Tout + node * DHH);
    if (HAS_SUB) {
        op[lane16] = f2h4(make_float4(2.f * acc.x - s.x, 2.f * acc.y - s.y,
                                      2.f * acc.z - s.z, 2.f * acc.w - s.w));
    } else {
        op[lane16] = f2h4(acc);
    }
}

// ---------------- fused GEMM: out = relu( sum_k T_k @ W_k + b ) ----------------
// block: 64 rows x 64 cols, 256 threads, 4x4 microtile, packed f32x2 FMA,
// register-buffered software pipeline over the 8 Chebyshev basis blocks.
// T read fp16 (converted to fp32 in smem); W/bias/accum fp32.
#define SPITCH 68   // floats per smem row (16B-aligned, padded)
template <bool LAST>
__global__ void __launch_bounds__(256) k_gemm(const float* __restrict__ Wl,
                                              const float* __restrict__ bl,
                                              float* __restrict__ outF,
                                              __half* __restrict__ outH) {
    __shared__ float Ts[64 * SPITCH];
    __shared__ float Ws[64 * SPITCH];
    int tid = threadIdx.x;
    int r0  = blockIdx.x * 64;
    int ty  = tid >> 4;     // 0..15 -> row group
    int tx  = tid & 15;     // 0..15 -> col group
    unsigned long long acc2[4][2] = {};
    bool full = (r0 + 64 <= NN);

    // each thread stages 4 chunks per tile: items i = tid + j*256, j=0..3
    // T chunk = 4 halfs (8B), W chunk = 4 floats (16B); both 16 chunks/row.
    int srow[4], sq[4];
#pragma unroll
    for (int j = 0; j < 4; j++) {
        int i = tid + j * 256;
        srow[j] = i >> 4;
        sq[j]   = i & 15;
    }

    uint2  tReg[4];
    float4 wReg[4];
    // preload k = 0
    {
        const __half* Tk = g_T[0];
        const float*  Wk = Wl;
#pragma unroll
        for (int j = 0; j < 4; j++) {
            int gr = r0 + srow[j];
            tReg[j] = (full || gr < NN) ? ((const uint2*)(Tk + gr * 64))[sq[j]]
                                        : make_uint2(0u, 0u);
            wReg[j] = ((const float4*)(Wk + srow[j] * 64))[sq[j]];
        }
    }

    for (int k = 0; k < KCH; k++) {
        // commit staged registers to smem (convert T to fp32)
        __syncthreads();
#pragma unroll
        for (int j = 0; j < 4; j++) {
            ((float4*)(Ts + srow[j] * SPITCH))[sq[j]] = h2f4(tReg[j]);
            ((float4*)(Ws + srow[j] * SPITCH))[sq[j]] = wReg[j];
        }
        __syncthreads();

        // prefetch k+1 while computing k
        if (k + 1 < KCH) {
            const __half* Tk = g_T[k + 1];
            const float*  Wk = Wl + (k + 1) * 64 * 64;
#pragma unroll
            for (int j = 0; j < 4; j++) {
                int gr = r0 + srow[j];
                tReg[j] = (full || gr < NN) ? ((const uint2*)(Tk + gr * 64))[sq[j]]
                                            : make_uint2(0u, 0u);
                wReg[j] = ((const float4*)(Wk + srow[j] * 64))[sq[j]];
            }
        }

#pragma unroll 8
        for (int f = 0; f < 64; f++) {
            ulonglong2 wv2 = *(const ulonglong2*)(Ws + f * SPITCH + tx * 4);
            unsigned long long tv2[4];
#pragma unroll
            for (int rr = 0; rr < 4; rr++)
                tv2[rr] = splat2(Ts[(ty * 4 + rr) * SPITCH + f]);
#pragma unroll
            for (int rr = 0; rr < 4; rr++) {
                acc2[rr][0] = ffma2(tv2[rr], wv2.x, acc2[rr][0]);
                acc2[rr][1] = ffma2(tv2[rr], wv2.y, acc2[rr][1]);
            }
        }
    }

    float4 bv = ((const float4*)bl)[tx];
#pragma unroll
    for (int rr = 0; rr < 4; rr++) {
        int gr = r0 + ty * 4 + rr;
        if (gr < NN) {
            float4 o;
            o.x = fmaxf(lo2(acc2[rr][0]) + bv.x, 0.f);
            o.y = fmaxf(hi2(acc2[rr][0]) + bv.y, 0.f);
            o.z = fmaxf(lo2(acc2[rr][1]) + bv.z, 0.f);
            o.w = fmaxf(hi2(acc2[rr][1]) + bv.w, 0.f);
            if (LAST) {
                stg_cs((float4*)(outF + gr * 64) + tx, o);  // final fp32, evict first
            } else {
                ((uint2*)(outH + gr * 64))[tx] = f2h4(o);   // next layer's T0 (fp16)
            }
        }
    }
}

// ---------------- launch ----------------
extern "C" void kernel_launch(void* const* d_in, const int* in_sizes, int n_in,
                              void* d_out, int out_size) {
    const float* x  = (const float*)d_in[0];
    const int*   ei = (const int*)d_in[1];
    const float* ew = (const float*)d_in[2];
    const float* W  = (const float*)d_in[3];
    const float* b  = (const float*)d_in[4];
    float* out = (float*)d_out;

    __half* Tbase = nullptr;
    cudaGetSymbolAddress((void**)&Tbase, g_T);
    auto Tk = [&](int k) { return Tbase + (size_t)k * NN * DHH; };

    const int TB = 256;
    int gN = (NN + TB - 1) / TB;
    int gE = (EE + TB - 1) / TB;
    int nb = (NN + 1023) / 1024;

    // CSR(dst) + edge norms
    k_zero<<<gN, TB>>>();
    k_degcnt<<<gE, TB>>>(ei, ew);
    k_dinv<<<gN, TB>>>();
    k_blocksum<<<nb, 1024>>>();
    k_scansums<<<1, 32>>>(nb);
    k_scanblock<<<nb, 1024>>>();
    k_fill<<<gE, TB>>>(ei, ew);

    // h -> T0 (fp16)
    k_copy<<<(NN * DHH / 4 + TB - 1) / TB, TB>>>((const float4*)x);

    int gProp = (NN * 16 + TB - 1) / TB;   // half-warp per node
    int gGemm = (NN + 63) / 64;

    for (int l = 0; l < LNUM; l++) {
        const float* Wl = W + (size_t)l * KCH * 64 * 64;
        const float* bl = b + l * 64;

        // T1 = L_hat @ T0
        k_prop<false><<<gProp, TB>>>(Tk(0), Tk(1), nullptr);
        // Tk = 2 * L_hat @ T(k-1) - T(k-2)
        for (int k = 2; k < KCH; k++)
            k_prop<true><<<gProp, TB>>>(Tk(k - 1), Tk(k), Tk(k - 2));

        if (l == LNUM - 1) k_gemm<true><<<gGemm, TB>>>(Wl, bl, out, nullptr);
        else               k_gemm<false><<<gGemm, TB>>>(Wl, bl, nullptr, Tk(0));
    }
}